// round 1
// baseline (speedup 1.0000x reference)
#include <cuda_runtime.h>

#define Bv 4
#define Nv 1024
#define CQv 128
#define CKVv 64
#define CPv 16
#define Hv 4
#define Dv 32
#define Tv (Bv*Nv)   // 4096 tokens

// ---------------- scratch (static __device__, no allocations) ----------------
__device__ float g_lnc[Tv*CKVv];       // ln(c)
__device__ float g_Yada[Tv*1536];      // lnc @ Wada (gate/skip for attn+trans, 3 blocks)
__device__ float g_Ysig[Tv*768];       // sigmoid(c @ Wsig + b) for attn/trans out gates
__device__ float g_ah[Tv*128];
__device__ float g_tt[Tv*128];
__device__ float g_qkvg[Tv*512];       // [q|k|v|gate]
__device__ float g_y2[Tv*512];         // [t@w1 | t@w2]
__device__ float g_obuf[Tv*128];       // gated attention out per token
__device__ float g_bm[Tv*256];
__device__ float g_r1[Tv*128];
__device__ float g_r2[Tv*128];
__device__ float g_Wada[64*1536];
__device__ float g_Wsig[64*768];
__device__ float g_bsig[768];
__device__ float g_Wqkvg[3*128*512];
__device__ float g_bqkv[3*512];
__device__ float g_W12[3*128*512];

__device__ __forceinline__ float sigmoidf_(float x) { return 1.f/(1.f+__expf(-x)); }

// ---------------- weight packing (runs every call; tiny) ----------------
__global__ void pack_kernel(
    const float* __restrict__ attn_s_gamma, const float* __restrict__ attn_gate_w,
    const float* __restrict__ attn_skip_w,
    const float* __restrict__ trans_s_gamma, const float* __restrict__ trans_gate_w,
    const float* __restrict__ trans_skip_w,
    const float* __restrict__ attn_ws_out, const float* __restrict__ attn_bs_out,
    const float* __restrict__ trans_ws_out, const float* __restrict__ trans_bs_out,
    const float* __restrict__ wq, const float* __restrict__ bq,
    const float* __restrict__ wk, const float* __restrict__ wv,
    const float* __restrict__ wg,
    const float* __restrict__ w1, const float* __restrict__ w2)
{
    int idx = blockIdx.x*blockDim.x + threadIdx.x;
    const int S0 = 64*1536;
    const int S1 = S0 + 64*768;
    const int S2 = S1 + 768;
    const int S3 = S2 + 3*128*512;
    const int S4 = S3 + 3*512;
    const int S5 = S4 + 3*128*512;
    if (idx < S0) {
        int k = idx/1536, col = idx%1536;
        int i = col>>9, r = col&511, m = r>>7, o = r&127;
        float v;
        if (m==0)      v = attn_gate_w[(i*64+k)*128+o]  * attn_s_gamma[i*64+k];
        else if (m==1) v = attn_skip_w[(i*64+k)*128+o]  * attn_s_gamma[i*64+k];
        else if (m==2) v = trans_gate_w[(i*64+k)*128+o] * trans_s_gamma[i*64+k];
        else           v = trans_skip_w[(i*64+k)*128+o] * trans_s_gamma[i*64+k];
        g_Wada[idx] = v;
    } else if (idx < S1) {
        int l = idx - S0; int k = l/768, col = l%768;
        int i = col/256, r = col%256, m = r>>7, o = r&127;
        g_Wsig[l] = (m==0) ? attn_ws_out[(i*64+k)*128+o] : trans_ws_out[(i*64+k)*128+o];
    } else if (idx < S2) {
        int col = idx - S1;
        int i = col/256, r = col%256, m = r>>7, o = r&127;
        g_bsig[col] = (m==0) ? attn_bs_out[i*128+o] : trans_bs_out[i*128+o];
    } else if (idx < S3) {
        int l = idx - S2; int i = l/(128*512); int rem = l%(128*512);
        int k = rem>>9, col = rem&511, m = col>>7, o = col&127;
        const float* src = (m==0)?wq:(m==1)?wk:(m==2)?wv:wg;
        g_Wqkvg[l] = src[(i*128+k)*128+o];
    } else if (idx < S4) {
        int l = idx - S3; int i = l>>9, col = l&511;
        g_bqkv[l] = (col<128) ? bq[i*128+col] : 0.f;
    } else if (idx < S5) {
        int l = idx - S4; int i = l/(128*512); int rem = l%(128*512);
        int k = rem>>9, col = rem&511;
        g_W12[l] = (col<256) ? w1[(i*128+k)*256+col] : w2[(i*128+k)*256+(col-256)];
    }
}

// ---------------- ln(c) over 64 channels ----------------
__global__ void lnc_kernel(const float* __restrict__ c)
{
    int tok = blockIdx.x, t = threadIdx.x;   // 64 threads
    float v = c[tok*64 + t];
    float s = v, sq = v*v;
    #pragma unroll
    for (int off = 16; off; off >>= 1) {
        s  += __shfl_xor_sync(0xffffffffu, s,  off);
        sq += __shfl_xor_sync(0xffffffffu, sq, off);
    }
    __shared__ float bs[2], bq2[2];
    int w = t >> 5;
    if ((t & 31) == 0) { bs[w] = s; bq2[w] = sq; }
    __syncthreads();
    s = bs[0] + bs[1]; sq = bq2[0] + bq2[1];
    float m = s * (1.f/64.f);
    float var = sq * (1.f/64.f) - m*m;
    g_lnc[tok*64 + t] = (v - m) * rsqrtf(var + 1e-5f);
}

// ---------------- adaln: produce ah and t for block `blk` ----------------
__global__ void adaln_kernel(const float* __restrict__ a_in, int blk)
{
    int tok = blockIdx.x, t = threadIdx.x;   // 128 threads
    float v = a_in[tok*128 + t];
    float s = v, sq = v*v;
    #pragma unroll
    for (int off = 16; off; off >>= 1) {
        s  += __shfl_xor_sync(0xffffffffu, s,  off);
        sq += __shfl_xor_sync(0xffffffffu, sq, off);
    }
    __shared__ float bs[4], bq2[4];
    int w = t >> 5;
    if ((t & 31) == 0) { bs[w] = s; bq2[w] = sq; }
    __syncthreads();
    s = bs[0]+bs[1]+bs[2]+bs[3]; sq = bq2[0]+bq2[1]+bq2[2]+bq2[3];
    float m = s * (1.f/128.f);
    float var = sq * (1.f/128.f) - m*m;
    float an = (v - m) * rsqrtf(var + 1e-5f);
    const float* yr = g_Yada + (size_t)tok*1536 + blk*512;
    g_ah[tok*128 + t] = sigmoidf_(yr[t])     * an + yr[128 + t];
    g_tt[tok*128 + t] = sigmoidf_(yr[256+t]) * an + yr[384 + t];
}

// ---------------- generic fp32 GEMM  C[M,N] = A[M,K] @ W[K,N] (+bias)(sigmoid) ----
__global__ void __launch_bounds__(256) sgemm_kernel(
    const float* __restrict__ A, int K,
    const float* __restrict__ W, int Ncols,
    float* __restrict__ C,
    const float* __restrict__ bias, int act)
{
    __shared__ float sA[64][65];
    __shared__ float sB[64][64];
    int m0 = blockIdx.y << 6, n0 = blockIdx.x << 6;
    int tid = threadIdx.x;
    int tx = tid & 15, ty = tid >> 4;
    int r0 = ty << 2, c0 = tx << 2;
    float acc[4][4];
    #pragma unroll
    for (int i = 0; i < 4; ++i)
        #pragma unroll
        for (int j = 0; j < 4; ++j) acc[i][j] = 0.f;

    for (int kt = 0; kt < K; kt += 64) {
        #pragma unroll
        for (int l = 0; l < 16; ++l) {
            int li = tid + (l << 8);
            int r = li >> 6, kk = li & 63;
            sA[r][kk] = A[(size_t)(m0 + r)*K + kt + kk];
            sB[r][kk] = W[(size_t)(kt + r)*Ncols + n0 + kk];
        }
        __syncthreads();
        #pragma unroll 16
        for (int kk = 0; kk < 64; ++kk) {
            float a0 = sA[r0+0][kk], a1 = sA[r0+1][kk];
            float a2 = sA[r0+2][kk], a3 = sA[r0+3][kk];
            float4 b = *(const float4*)&sB[kk][c0];
            acc[0][0] += a0*b.x; acc[0][1] += a0*b.y; acc[0][2] += a0*b.z; acc[0][3] += a0*b.w;
            acc[1][0] += a1*b.x; acc[1][1] += a1*b.y; acc[1][2] += a1*b.z; acc[1][3] += a1*b.w;
            acc[2][0] += a2*b.x; acc[2][1] += a2*b.y; acc[2][2] += a2*b.z; acc[2][3] += a2*b.w;
            acc[3][0] += a3*b.x; acc[3][1] += a3*b.y; acc[3][2] += a3*b.z; acc[3][3] += a3*b.w;
        }
        __syncthreads();
    }
    #pragma unroll
    for (int i = 0; i < 4; ++i) {
        #pragma unroll
        for (int j = 0; j < 4; ++j) {
            float v = acc[i][j];
            int n = n0 + c0 + j;
            if (bias) v += bias[n];
            if (act)  v = 1.f/(1.f+__expf(-v));
            C[(size_t)(m0 + r0 + i)*Ncols + n] = v;
        }
    }
}

// ---------------- local attention + pair bias (exact; mask underflows to 0) ----
__global__ void __launch_bounds__(256) attn_kernel(
    const float* __restrict__ p,
    const float* __restrict__ lnz_g, const float* __restrict__ lnz_b,
    const float* __restrict__ wb)
{
    extern __shared__ float sm[];
    float* sQ  = sm;                       // 32*128
    float* sKV = sQ + 32*128;              // 128*129 (padded)
    float* sS  = sKV + 128*129;            // 4*32*128
    float* sPar= sS + 4*32*128;            // 96: lnz_g[16], lnz_b[16], wb[64]
    int j = blockIdx.x, b = blockIdx.y;
    int tid = threadIdx.x;
    int k0 = 32*j - 48;
    int q0 = 32*j;
    const float scale = 0.17677669529663687f;  // 1/sqrt(32)

    if (tid < 16) { sPar[tid] = lnz_g[tid]; sPar[16+tid] = lnz_b[tid]; }
    if (tid < 64) sPar[32+tid] = wb[tid];

    for (int e = tid; e < 32*128; e += 256) {
        int row = e >> 7, col = e & 127;
        sQ[e] = g_qkvg[((size_t)(b*Nv + q0 + row))*512 + col] * scale;
    }
    for (int e = tid; e < 128*128; e += 256) {
        int kk = e >> 7, col = e & 127;
        int gk = k0 + kk;
        float v = 0.f;
        if (gk >= 0 && gk < Nv) v = g_qkvg[((size_t)(b*Nv + gk))*512 + 128 + col];
        sKV[kk*129 + col] = v;
    }
    __syncthreads();

    // scores = q.k (masked)
    for (int e = tid; e < 4*32*128; e += 256) {
        int k = e & 127, qq = (e >> 7) & 31, h = e >> 12;
        int gk = k0 + k;
        float acc = -1e30f;
        if (gk >= 0 && gk < Nv) {
            acc = 0.f;
            const float* qp = sQ + qq*128 + h*32;
            const float* kp = sKV + k*129 + h*32;
            #pragma unroll
            for (int d = 0; d < 32; ++d) acc += qp[d]*kp[d];
        }
        sS[e] = acc;   // e == h*4096 + qq*128 + k
    }
    __syncthreads();

    // add pair bias zb = (ln(p)*g + b) @ wb[:,h]
    for (int pr = tid; pr < 32*128; pr += 256) {
        int qq = pr >> 7, k = pr & 127;
        int gk = k0 + k;
        if (gk < 0 || gk >= Nv) continue;
        const float* pp = p + (((size_t)(b*Nv + q0 + qq))*Nv + gk)*16;
        float vals[16];
        #pragma unroll
        for (int c4 = 0; c4 < 4; ++c4) {
            float4 f = ((const float4*)pp)[c4];
            vals[c4*4+0]=f.x; vals[c4*4+1]=f.y; vals[c4*4+2]=f.z; vals[c4*4+3]=f.w;
        }
        float s = 0.f, sq = 0.f;
        #pragma unroll
        for (int cc = 0; cc < 16; ++cc) { s += vals[cc]; sq += vals[cc]*vals[cc]; }
        float m = s*(1.f/16.f), var = sq*(1.f/16.f) - m*m;
        float rs = rsqrtf(var + 1e-5f);
        #pragma unroll
        for (int cc = 0; cc < 16; ++cc) vals[cc] = (vals[cc]-m)*rs*sPar[cc] + sPar[16+cc];
        #pragma unroll
        for (int h = 0; h < 4; ++h) {
            float zb = 0.f;
            #pragma unroll
            for (int cc = 0; cc < 16; ++cc) zb += vals[cc]*sPar[32 + cc*4 + h];
            sS[h*4096 + qq*128 + k] += zb;
        }
    }
    __syncthreads();

    // softmax over 128 keys; one warp per row
    int w = tid >> 5, lane = tid & 31;
    for (int it = 0; it < 16; ++it) {
        int row = it*8 + w;
        float* rp = sS + row*128;
        float v0 = rp[lane], v1 = rp[lane+32], v2 = rp[lane+64], v3 = rp[lane+96];
        float mx = fmaxf(fmaxf(v0,v1), fmaxf(v2,v3));
        #pragma unroll
        for (int off = 16; off; off >>= 1) mx = fmaxf(mx, __shfl_xor_sync(0xffffffffu, mx, off));
        v0 = __expf(v0-mx); v1 = __expf(v1-mx); v2 = __expf(v2-mx); v3 = __expf(v3-mx);
        float sum = v0+v1+v2+v3;
        #pragma unroll
        for (int off = 16; off; off >>= 1) sum += __shfl_xor_sync(0xffffffffu, sum, off);
        float inv = 1.f/sum;
        rp[lane]=v0*inv; rp[lane+32]=v1*inv; rp[lane+64]=v2*inv; rp[lane+96]=v3*inv;
    }
    __syncthreads();

    // reload V into sKV
    for (int e = tid; e < 128*128; e += 256) {
        int kk = e >> 7, col = e & 127;
        int gk = k0 + kk;
        float v = 0.f;
        if (gk >= 0 && gk < Nv) v = g_qkvg[((size_t)(b*Nv + gk))*512 + 256 + col];
        sKV[kk*129 + col] = v;
    }
    __syncthreads();

    // o = w @ v, apply sigmoid gate, store
    for (int e = tid; e < 32*128; e += 256) {
        int qq = e >> 7, col = e & 127, h = col >> 5;
        const float* wp = sS + h*4096 + qq*128;
        float acc = 0.f;
        #pragma unroll 8
        for (int k = 0; k < 128; ++k) acc += wp[k]*sKV[k*129 + col];
        size_t tok = (size_t)(b*Nv + q0 + qq);
        float gt = g_qkvg[tok*512 + 384 + col];
        g_obuf[tok*128 + col] = acc * sigmoidf_(gt);
    }
}

// ---------------- SwiGLU elementwise ----------------
__global__ void bm_kernel()
{
    int idx = blockIdx.x*blockDim.x + threadIdx.x;
    if (idx >= Tv*256) return;
    int tok = idx >> 8, jj = idx & 255;
    float x = g_y2[(size_t)tok*512 + jj];
    float y = g_y2[(size_t)tok*512 + 256 + jj];
    g_bm[idx] = x * sigmoidf_(x) * y;
}

// ---------------- final combine: a_new = sigA*(o@wo) + sigT*(bm@wout) ----------
__global__ void final_kernel(float* __restrict__ out, int blk)
{
    int tok = blockIdx.x, t = threadIdx.x;   // 128 threads
    const float* ys = g_Ysig + (size_t)tok*768 + blk*256;
    out[tok*128 + t] = ys[t]*g_r1[tok*128+t] + ys[128+t]*g_r2[tok*128+t];
}

// ---------------- launch ----------------
extern "C" void kernel_launch(void* const* d_in, const int* in_sizes, int n_in,
                              void* d_out, int out_size)
{
    const float* q            = (const float*)d_in[0];
    const float* c            = (const float*)d_in[1];
    const float* p            = (const float*)d_in[2];
    const float* attn_s_gamma = (const float*)d_in[3];
    const float* attn_gate_w  = (const float*)d_in[4];
    const float* attn_skip_w  = (const float*)d_in[5];
    const float* attn_wq      = (const float*)d_in[6];
    const float* attn_bq      = (const float*)d_in[7];
    const float* attn_wk      = (const float*)d_in[8];
    const float* attn_wv      = (const float*)d_in[9];
    const float* attn_lnz_g   = (const float*)d_in[10];
    const float* attn_lnz_b   = (const float*)d_in[11];
    const float* attn_wb      = (const float*)d_in[12];
    const float* attn_wgate   = (const float*)d_in[13];
    const float* attn_wo      = (const float*)d_in[14];
    const float* attn_ws_out  = (const float*)d_in[15];
    const float* attn_bs_out  = (const float*)d_in[16];
    const float* trans_s_gamma= (const float*)d_in[17];
    const float* trans_gate_w = (const float*)d_in[18];
    const float* trans_skip_w = (const float*)d_in[19];
    const float* trans_w1     = (const float*)d_in[20];
    const float* trans_w2     = (const float*)d_in[21];
    const float* trans_wout   = (const float*)d_in[22];
    const float* trans_ws_out = (const float*)d_in[23];
    const float* trans_bs_out = (const float*)d_in[24];
    float* out = (float*)d_out;

    float *p_lnc, *p_Yada, *p_Ysig, *p_ah, *p_tt, *p_qkvg, *p_y2, *p_obuf, *p_bm, *p_r1, *p_r2;
    float *p_Wada, *p_Wsig, *p_bsig, *p_Wqkvg, *p_bqkv, *p_W12;
    cudaGetSymbolAddress((void**)&p_lnc,  g_lnc);
    cudaGetSymbolAddress((void**)&p_Yada, g_Yada);
    cudaGetSymbolAddress((void**)&p_Ysig, g_Ysig);
    cudaGetSymbolAddress((void**)&p_ah,   g_ah);
    cudaGetSymbolAddress((void**)&p_tt,   g_tt);
    cudaGetSymbolAddress((void**)&p_qkvg, g_qkvg);
    cudaGetSymbolAddress((void**)&p_y2,   g_y2);
    cudaGetSymbolAddress((void**)&p_obuf, g_obuf);
    cudaGetSymbolAddress((void**)&p_bm,   g_bm);
    cudaGetSymbolAddress((void**)&p_r1,   g_r1);
    cudaGetSymbolAddress((void**)&p_r2,   g_r2);
    cudaGetSymbolAddress((void**)&p_Wada, g_Wada);
    cudaGetSymbolAddress((void**)&p_Wsig, g_Wsig);
    cudaGetSymbolAddress((void**)&p_bsig, g_bsig);
    cudaGetSymbolAddress((void**)&p_Wqkvg,g_Wqkvg);
    cudaGetSymbolAddress((void**)&p_bqkv, g_bqkv);
    cudaGetSymbolAddress((void**)&p_W12,  g_W12);

    const int PACK_TOTAL = 64*1536 + 64*768 + 768 + 3*128*512 + 3*512 + 3*128*512;
    pack_kernel<<<(PACK_TOTAL + 255)/256, 256>>>(
        attn_s_gamma, attn_gate_w, attn_skip_w,
        trans_s_gamma, trans_gate_w, trans_skip_w,
        attn_ws_out, attn_bs_out, trans_ws_out, trans_bs_out,
        attn_wq, attn_bq, attn_wk, attn_wv, attn_wgate,
        trans_w1, trans_w2);

    lnc_kernel<<<Tv, 64>>>(c);
    // Yada = lnc @ Wada  [4096,1536]
    sgemm_kernel<<<dim3(1536/64, Tv/64), 256>>>(p_lnc, 64, p_Wada, 1536, p_Yada, nullptr, 0);
    // Ysig = sigmoid(c @ Wsig + bsig)  [4096,768]
    sgemm_kernel<<<dim3(768/64, Tv/64), 256>>>(c, 64, p_Wsig, 768, p_Ysig, p_bsig, 1);

    const int ATTN_SMEM = (32*128 + 128*129 + 4*32*128 + 96) * 4;
    cudaFuncSetAttribute(attn_kernel, cudaFuncAttributeMaxDynamicSharedMemorySize, ATTN_SMEM);

    for (int i = 0; i < 3; ++i) {
        const float* a_in = (i == 0) ? q : (const float*)out;
        adaln_kernel<<<Tv, 128>>>(a_in, i);
        // qkvg = ah @ [wq|wk|wv|wgate] + [bq|0|0|0]
        sgemm_kernel<<<dim3(8, Tv/64), 256>>>(p_ah, 128, p_Wqkvg + (size_t)i*128*512, 512,
                                              p_qkvg, p_bqkv + i*512, 0);
        // y2 = t @ [w1|w2]
        sgemm_kernel<<<dim3(8, Tv/64), 256>>>(p_tt, 128, p_W12 + (size_t)i*128*512, 512,
                                              p_y2, nullptr, 0);
        attn_kernel<<<dim3(32, Bv), 256, ATTN_SMEM>>>(p, attn_lnz_g + i*16,
                                                      attn_lnz_b + i*16, attn_wb + i*64);
        bm_kernel<<<(Tv*256)/256, 256>>>();
        // r1 = o @ wo ; r2 = bm @ wout (raw weights are already [K][N] row-major)
        sgemm_kernel<<<dim3(2, Tv/64), 256>>>(p_obuf, 128, attn_wo + (size_t)i*128*128, 128,
                                              p_r1, nullptr, 0);
        sgemm_kernel<<<dim3(2, Tv/64), 256>>>(p_bm, 256, trans_wout + (size_t)i*256*128, 128,
                                              p_r2, nullptr, 0);
        final_kernel<<<Tv, 128>>>(out, i);
    }
}

// round 2
// speedup vs baseline: 1.4032x; 1.4032x over previous
#include <cuda_runtime.h>
#include <cstdint>

#define Bv 4
#define Nv 1024
#define CQv 128
#define CKVv 64
#define CPv 16
#define Hv 4
#define Dv 32
#define Tv (Bv*Nv)   // 4096 tokens

// ---------------- scratch (static __device__, no allocations) ----------------
__device__ float g_lnc[Tv*CKVv];
__device__ float g_Yada[Tv*1536];
__device__ float g_Ysig[Tv*768];
__device__ float g_ah[Tv*128];
__device__ float g_tt[Tv*128];
__device__ float g_qkvg[Tv*512];
__device__ float g_y2[Tv*512];
__device__ float g_obuf[Tv*128];
__device__ float g_bm[Tv*256];
__device__ float g_r1[Tv*128];
__device__ float g_r2[Tv*128];
__device__ float g_Wada[64*1536];
__device__ float g_Wsig[64*768];
__device__ float g_bsig[768];
__device__ float g_Wqkvg[3*128*512];
__device__ float g_bqkv[3*512];
__device__ float g_W12[3*128*512];

__device__ __forceinline__ float sigmoidf_(float x) { return 1.f/(1.f+__expf(-x)); }
__device__ __forceinline__ float tf32r_(float x) {
    uint32_t u; asm("cvt.rna.tf32.f32 %0, %1;" : "=r"(u) : "f"(x));
    return __uint_as_float(u);
}

// ---------------- weight packing ----------------
__global__ void pack_kernel(
    const float* __restrict__ attn_s_gamma, const float* __restrict__ attn_gate_w,
    const float* __restrict__ attn_skip_w,
    const float* __restrict__ trans_s_gamma, const float* __restrict__ trans_gate_w,
    const float* __restrict__ trans_skip_w,
    const float* __restrict__ attn_ws_out, const float* __restrict__ attn_bs_out,
    const float* __restrict__ trans_ws_out, const float* __restrict__ trans_bs_out,
    const float* __restrict__ wq, const float* __restrict__ bq,
    const float* __restrict__ wk, const float* __restrict__ wv,
    const float* __restrict__ wg,
    const float* __restrict__ w1, const float* __restrict__ w2)
{
    int idx = blockIdx.x*blockDim.x + threadIdx.x;
    const int S0 = 64*1536;
    const int S1 = S0 + 64*768;
    const int S2 = S1 + 768;
    const int S3 = S2 + 3*128*512;
    const int S4 = S3 + 3*512;
    const int S5 = S4 + 3*128*512;
    if (idx < S0) {
        int k = idx/1536, col = idx%1536;
        int i = col>>9, r = col&511, m = r>>7, o = r&127;
        float v;
        if (m==0)      v = attn_gate_w[(i*64+k)*128+o]  * attn_s_gamma[i*64+k];
        else if (m==1) v = attn_skip_w[(i*64+k)*128+o]  * attn_s_gamma[i*64+k];
        else if (m==2) v = trans_gate_w[(i*64+k)*128+o] * trans_s_gamma[i*64+k];
        else           v = trans_skip_w[(i*64+k)*128+o] * trans_s_gamma[i*64+k];
        g_Wada[idx] = v;
    } else if (idx < S1) {
        int l = idx - S0; int k = l/768, col = l%768;
        int i = col/256, r = col%256, m = r>>7, o = r&127;
        g_Wsig[l] = (m==0) ? attn_ws_out[(i*64+k)*128+o] : trans_ws_out[(i*64+k)*128+o];
    } else if (idx < S2) {
        int col = idx - S1;
        int i = col/256, r = col%256, m = r>>7, o = r&127;
        g_bsig[col] = (m==0) ? attn_bs_out[i*128+o] : trans_bs_out[i*128+o];
    } else if (idx < S3) {
        int l = idx - S2; int i = l/(128*512); int rem = l%(128*512);
        int k = rem>>9, col = rem&511, m = col>>7, o = col&127;
        const float* src = (m==0)?wq:(m==1)?wk:(m==2)?wv:wg;
        g_Wqkvg[l] = src[(i*128+k)*128+o];
    } else if (idx < S4) {
        int l = idx - S3; int i = l>>9, col = l&511;
        g_bqkv[l] = (col<128) ? bq[i*128+col] : 0.f;
    } else if (idx < S5) {
        int l = idx - S4; int i = l/(128*512); int rem = l%(128*512);
        int k = rem>>9, col = rem&511;
        g_W12[l] = (col<256) ? w1[(i*128+k)*256+col] : w2[(i*128+k)*256+(col-256)];
    }
}

// ---------------- ln(c) ----------------
__global__ void lnc_kernel(const float* __restrict__ c)
{
    int tok = blockIdx.x, t = threadIdx.x;   // 64 threads
    float v = c[tok*64 + t];
    float s = v, sq = v*v;
    #pragma unroll
    for (int off = 16; off; off >>= 1) {
        s  += __shfl_xor_sync(0xffffffffu, s,  off);
        sq += __shfl_xor_sync(0xffffffffu, sq, off);
    }
    __shared__ float bs[2], bq2[2];
    int w = t >> 5;
    if ((t & 31) == 0) { bs[w] = s; bq2[w] = sq; }
    __syncthreads();
    s = bs[0] + bs[1]; sq = bq2[0] + bq2[1];
    float m = s * (1.f/64.f);
    float var = sq * (1.f/64.f) - m*m;
    g_lnc[tok*64 + t] = (v - m) * rsqrtf(var + 1e-5f);
}

// ---------------- adaln ----------------
__global__ void adaln_kernel(const float* __restrict__ a_in, int blk)
{
    int tok = blockIdx.x, t = threadIdx.x;   // 128 threads
    float v = a_in[tok*128 + t];
    float s = v, sq = v*v;
    #pragma unroll
    for (int off = 16; off; off >>= 1) {
        s  += __shfl_xor_sync(0xffffffffu, s,  off);
        sq += __shfl_xor_sync(0xffffffffu, sq, off);
    }
    __shared__ float bs[4], bq2[4];
    int w = t >> 5;
    if ((t & 31) == 0) { bs[w] = s; bq2[w] = sq; }
    __syncthreads();
    s = bs[0]+bs[1]+bs[2]+bs[3]; sq = bq2[0]+bq2[1]+bq2[2]+bq2[3];
    float m = s * (1.f/128.f);
    float var = sq * (1.f/128.f) - m*m;
    float an = (v - m) * rsqrtf(var + 1e-5f);
    const float* yr = g_Yada + (size_t)tok*1536 + blk*512;
    g_ah[tok*128 + t] = sigmoidf_(yr[t])     * an + yr[128 + t];
    g_tt[tok*128 + t] = sigmoidf_(yr[256+t]) * an + yr[384 + t];
}

// ------------- tf32 tensor-core GEMM C[M,N]=A[M,K]@W[K,N] (+bias)(sigmoid) ----
// CTA tile 128x128, 8 warps (2x4), warp tile 64x32 = 4x4 m16n8k8 mma.
__global__ void __launch_bounds__(256) tgemm_kernel(
    const float* __restrict__ A, int K,
    const float* __restrict__ W, int Ncols,
    float* __restrict__ C,
    const float* __restrict__ bias, int act)
{
    __shared__ float sA[128][36];
    __shared__ float sB[32][132];
    int m0 = blockIdx.y << 7, n0 = blockIdx.x << 7;
    int tid = threadIdx.x, lane = tid & 31, w = tid >> 5;
    int wm = (w & 1) << 6, wn = (w >> 1) << 5;
    int g = lane >> 2, tig = lane & 3;

    float acc[4][4][4];
    #pragma unroll
    for (int mt = 0; mt < 4; ++mt)
        #pragma unroll
        for (int nt = 0; nt < 4; ++nt)
            #pragma unroll
            for (int r = 0; r < 4; ++r) acc[mt][nt][r] = 0.f;

    for (int kt = 0; kt < K; kt += 32) {
        #pragma unroll
        for (int l = 0; l < 4; ++l) {
            int idx = tid + (l << 8);
            int r = idx >> 3, c4 = (idx & 7) << 2;
            float4 v = *(const float4*)&A[(size_t)(m0 + r)*K + kt + c4];
            sA[r][c4+0] = tf32r_(v.x); sA[r][c4+1] = tf32r_(v.y);
            sA[r][c4+2] = tf32r_(v.z); sA[r][c4+3] = tf32r_(v.w);
        }
        #pragma unroll
        for (int l = 0; l < 4; ++l) {
            int idx = tid + (l << 8);
            int r = idx >> 5, c4 = (idx & 31) << 2;
            float4 v = *(const float4*)&W[(size_t)(kt + r)*Ncols + n0 + c4];
            sB[r][c4+0] = tf32r_(v.x); sB[r][c4+1] = tf32r_(v.y);
            sB[r][c4+2] = tf32r_(v.z); sB[r][c4+3] = tf32r_(v.w);
        }
        __syncthreads();
        #pragma unroll
        for (int ks = 0; ks < 4; ++ks) {
            int k0 = ks << 3;
            uint32_t af[4][4], bf[4][2];
            #pragma unroll
            for (int mt = 0; mt < 4; ++mt) {
                int row = wm + (mt << 4);
                af[mt][0] = __float_as_uint(sA[row+g  ][k0+tig  ]);
                af[mt][1] = __float_as_uint(sA[row+g+8][k0+tig  ]);
                af[mt][2] = __float_as_uint(sA[row+g  ][k0+tig+4]);
                af[mt][3] = __float_as_uint(sA[row+g+8][k0+tig+4]);
            }
            #pragma unroll
            for (int nt = 0; nt < 4; ++nt) {
                int col = wn + (nt << 3);
                bf[nt][0] = __float_as_uint(sB[k0+tig  ][col+g]);
                bf[nt][1] = __float_as_uint(sB[k0+tig+4][col+g]);
            }
            #pragma unroll
            for (int mt = 0; mt < 4; ++mt)
                #pragma unroll
                for (int nt = 0; nt < 4; ++nt) {
                    asm volatile(
                        "mma.sync.aligned.m16n8k8.row.col.f32.tf32.tf32.f32 "
                        "{%0,%1,%2,%3}, {%4,%5,%6,%7}, {%8,%9}, {%0,%1,%2,%3};"
                        : "+f"(acc[mt][nt][0]), "+f"(acc[mt][nt][1]),
                          "+f"(acc[mt][nt][2]), "+f"(acc[mt][nt][3])
                        : "r"(af[mt][0]), "r"(af[mt][1]), "r"(af[mt][2]), "r"(af[mt][3]),
                          "r"(bf[nt][0]), "r"(bf[nt][1]));
                }
        }
        __syncthreads();
    }
    #pragma unroll
    for (int mt = 0; mt < 4; ++mt) {
        #pragma unroll
        for (int nt = 0; nt < 4; ++nt) {
            int row = m0 + wm + (mt << 4) + g;
            int col = n0 + wn + (nt << 3) + 2*tig;
            float v0 = acc[mt][nt][0], v1 = acc[mt][nt][1];
            float v2 = acc[mt][nt][2], v3 = acc[mt][nt][3];
            if (bias) { float b0 = bias[col], b1 = bias[col+1]; v0 += b0; v1 += b1; v2 += b0; v3 += b1; }
            if (act)  { v0 = sigmoidf_(v0); v1 = sigmoidf_(v1); v2 = sigmoidf_(v2); v3 = sigmoidf_(v3); }
            *(float2*)&C[(size_t)row*Ncols + col]     = make_float2(v0, v1);
            *(float2*)&C[(size_t)(row+8)*Ncols + col] = make_float2(v2, v3);
        }
    }
}

// ---------------- local attention + pair bias ----------------
#define KVS 132                 // sKV row stride (floats)
#define HSTRIDE 4228            // 32*132 + 4 : bank-skew across heads
__global__ void __launch_bounds__(256) attn_kernel(
    const float* __restrict__ p,
    const float* __restrict__ lnz_g, const float* __restrict__ lnz_b,
    const float* __restrict__ wb)
{
    extern __shared__ float sm[];
    float* sQ  = sm;                       // 32*128
    float* sKV = sQ + 32*128;              // 128*KVS
    float* sS  = sKV + 128*KVS;            // 4*HSTRIDE
    float* sPar= sS + 4*HSTRIDE;           // 96
    int j = blockIdx.x, b = blockIdx.y;
    int tid = threadIdx.x;
    int w = tid >> 5, lane = tid & 31;
    int k0 = 32*j - 48;
    int q0 = 32*j;
    const float scale = 0.17677669529663687f;

    if (tid < 16) { sPar[tid] = lnz_g[tid]; sPar[16+tid] = lnz_b[tid]; }
    if (tid >= 32 && tid < 96) sPar[tid] = wb[tid-32];

    for (int e = tid; e < 32*128; e += 256) {
        int row = e >> 7, col = e & 127;
        sQ[e] = g_qkvg[((size_t)(b*Nv + q0 + row))*512 + col] * scale;
    }
    for (int e = tid; e < 128*128; e += 256) {
        int kk = e >> 7, col = e & 127;
        int gk = k0 + kk;
        float v = 0.f;
        if (gk >= 0 && gk < Nv) v = g_qkvg[((size_t)(b*Nv + gk))*512 + 128 + col];
        sKV[kk*KVS + col] = v;
    }
    __syncthreads();

    // scores: warp task = (h, k-chunk); K rows in registers, Q broadcast
    #pragma unroll
    for (int it = 0; it < 2; ++it) {
        int task = it*8 + w;
        int h = task & 3, kq = task >> 2;
        int k = kq*32 + lane;
        int gk = k0 + k;
        bool valid = (gk >= 0 && gk < Nv);
        float4 kr[8];
        #pragma unroll
        for (int jj = 0; jj < 8; ++jj)
            kr[jj] = *(const float4*)&sKV[k*KVS + h*32 + jj*4];
        float* srow = sS + h*HSTRIDE;
        for (int qq = 0; qq < 32; ++qq) {
            float a = 0.f;
            const float4* qp = (const float4*)&sQ[qq*128 + h*32];
            #pragma unroll
            for (int jj = 0; jj < 8; ++jj) {
                float4 qf = qp[jj];
                a += qf.x*kr[jj].x + qf.y*kr[jj].y + qf.z*kr[jj].z + qf.w*kr[jj].w;
            }
            srow[qq*132 + k] = valid ? a : -1e30f;
        }
    }
    __syncthreads();

    // pair bias
    for (int pr = tid; pr < 32*128; pr += 256) {
        int qq = pr >> 7, k = pr & 127;
        int gk = k0 + k;
        if (gk < 0 || gk >= Nv) continue;
        const float* pp = p + (((size_t)(b*Nv + q0 + qq))*Nv + gk)*16;
        float vals[16];
        #pragma unroll
        for (int c4 = 0; c4 < 4; ++c4) {
            float4 f = ((const float4*)pp)[c4];
            vals[c4*4+0]=f.x; vals[c4*4+1]=f.y; vals[c4*4+2]=f.z; vals[c4*4+3]=f.w;
        }
        float s = 0.f, sq = 0.f;
        #pragma unroll
        for (int cc = 0; cc < 16; ++cc) { s += vals[cc]; sq += vals[cc]*vals[cc]; }
        float m = s*(1.f/16.f), var = sq*(1.f/16.f) - m*m;
        float rs = rsqrtf(var + 1e-5f);
        #pragma unroll
        for (int cc = 0; cc < 16; ++cc) vals[cc] = (vals[cc]-m)*rs*sPar[cc] + sPar[16+cc];
        #pragma unroll
        for (int h = 0; h < 4; ++h) {
            float zb = 0.f;
            #pragma unroll
            for (int cc = 0; cc < 16; ++cc) zb += vals[cc]*sPar[32 + cc*4 + h];
            sS[h*HSTRIDE + qq*132 + k] += zb;
        }
    }
    __syncthreads();

    // softmax over 128 keys; one warp per row
    for (int it = 0; it < 16; ++it) {
        int row = it*8 + w;
        float* rp = sS + (row >> 5)*HSTRIDE + (row & 31)*132;
        float v0 = rp[lane], v1 = rp[lane+32], v2 = rp[lane+64], v3 = rp[lane+96];
        float mx = fmaxf(fmaxf(v0,v1), fmaxf(v2,v3));
        #pragma unroll
        for (int off = 16; off; off >>= 1) mx = fmaxf(mx, __shfl_xor_sync(0xffffffffu, mx, off));
        v0 = __expf(v0-mx); v1 = __expf(v1-mx); v2 = __expf(v2-mx); v3 = __expf(v3-mx);
        float sum = v0+v1+v2+v3;
        #pragma unroll
        for (int off = 16; off; off >>= 1) sum += __shfl_xor_sync(0xffffffffu, sum, off);
        float inv = 1.f/sum;
        rp[lane]=v0*inv; rp[lane+32]=v1*inv; rp[lane+64]=v2*inv; rp[lane+96]=v3*inv;
    }
    __syncthreads();

    // reload V
    for (int e = tid; e < 128*128; e += 256) {
        int kk = e >> 7, col = e & 127;
        int gk = k0 + kk;
        float v = 0.f;
        if (gk >= 0 && gk < Nv) v = g_qkvg[((size_t)(b*Nv + gk))*512 + 256 + col];
        sKV[kk*KVS + col] = v;
    }
    __syncthreads();

    // o = w @ v : each warp handles 4 queries; lane covers 4 cols
    {
        int qq0 = w << 2;
        int h = lane >> 3;
        float4 acc0 = {0,0,0,0}, acc1 = {0,0,0,0}, acc2 = {0,0,0,0}, acc3 = {0,0,0,0};
        const float* wsb = sS + h*HSTRIDE;
        #pragma unroll 4
        for (int k = 0; k < 128; ++k) {
            float4 vv = *(const float4*)&sKV[k*KVS + lane*4];
            float w0 = wsb[(qq0+0)*132 + k];
            float w1 = wsb[(qq0+1)*132 + k];
            float w2 = wsb[(qq0+2)*132 + k];
            float w3 = wsb[(qq0+3)*132 + k];
            acc0.x += vv.x*w0; acc0.y += vv.y*w0; acc0.z += vv.z*w0; acc0.w += vv.w*w0;
            acc1.x += vv.x*w1; acc1.y += vv.y*w1; acc1.z += vv.z*w1; acc1.w += vv.w*w1;
            acc2.x += vv.x*w2; acc2.y += vv.y*w2; acc2.z += vv.z*w2; acc2.w += vv.w*w2;
            acc3.x += vv.x*w3; acc3.y += vv.y*w3; acc3.z += vv.z*w3; acc3.w += vv.w*w3;
        }
        float4 accs[4] = {acc0, acc1, acc2, acc3};
        #pragma unroll
        for (int qi = 0; qi < 4; ++qi) {
            size_t tok = (size_t)(b*Nv + q0 + qq0 + qi);
            float4 gt = *(const float4*)&g_qkvg[tok*512 + 384 + lane*4];
            float4 o;
            o.x = accs[qi].x * sigmoidf_(gt.x);
            o.y = accs[qi].y * sigmoidf_(gt.y);
            o.z = accs[qi].z * sigmoidf_(gt.z);
            o.w = accs[qi].w * sigmoidf_(gt.w);
            *(float4*)&g_obuf[tok*128 + lane*4] = o;
        }
    }
}

// ---------------- SwiGLU elementwise ----------------
__global__ void bm_kernel()
{
    int idx = blockIdx.x*blockDim.x + threadIdx.x;
    if (idx >= Tv*256) return;
    int tok = idx >> 8, jj = idx & 255;
    float x = g_y2[(size_t)tok*512 + jj];
    float y = g_y2[(size_t)tok*512 + 256 + jj];
    g_bm[idx] = x * sigmoidf_(x) * y;
}

// ---------------- final combine ----------------
__global__ void final_kernel(float* __restrict__ out, int blk)
{
    int tok = blockIdx.x, t = threadIdx.x;   // 128 threads
    const float* ys = g_Ysig + (size_t)tok*768 + blk*256;
    out[tok*128 + t] = ys[t]*g_r1[tok*128+t] + ys[128+t]*g_r2[tok*128+t];
}

// ---------------- launch ----------------
extern "C" void kernel_launch(void* const* d_in, const int* in_sizes, int n_in,
                              void* d_out, int out_size)
{
    const float* q            = (const float*)d_in[0];
    const float* c            = (const float*)d_in[1];
    const float* p            = (const float*)d_in[2];
    const float* attn_s_gamma = (const float*)d_in[3];
    const float* attn_gate_w  = (const float*)d_in[4];
    const float* attn_skip_w  = (const float*)d_in[5];
    const float* attn_wq      = (const float*)d_in[6];
    const float* attn_bq      = (const float*)d_in[7];
    const float* attn_wk      = (const float*)d_in[8];
    const float* attn_wv      = (const float*)d_in[9];
    const float* attn_lnz_g   = (const float*)d_in[10];
    const float* attn_lnz_b   = (const float*)d_in[11];
    const float* attn_wb      = (const float*)d_in[12];
    const float* attn_wgate   = (const float*)d_in[13];
    const float* attn_wo      = (const float*)d_in[14];
    const float* attn_ws_out  = (const float*)d_in[15];
    const float* attn_bs_out  = (const float*)d_in[16];
    const float* trans_s_gamma= (const float*)d_in[17];
    const float* trans_gate_w = (const float*)d_in[18];
    const float* trans_skip_w = (const float*)d_in[19];
    const float* trans_w1     = (const float*)d_in[20];
    const float* trans_w2     = (const float*)d_in[21];
    const float* trans_wout   = (const float*)d_in[22];
    const float* trans_ws_out = (const float*)d_in[23];
    const float* trans_bs_out = (const float*)d_in[24];
    float* out = (float*)d_out;

    float *p_lnc, *p_Yada, *p_Ysig, *p_ah, *p_tt, *p_qkvg, *p_obuf, *p_bm, *p_r1, *p_r2;
    float *p_Wada, *p_Wsig, *p_bsig, *p_Wqkvg, *p_bqkv, *p_W12;
    cudaGetSymbolAddress((void**)&p_lnc,  g_lnc);
    cudaGetSymbolAddress((void**)&p_Yada, g_Yada);
    cudaGetSymbolAddress((void**)&p_Ysig, g_Ysig);
    cudaGetSymbolAddress((void**)&p_ah,   g_ah);
    cudaGetSymbolAddress((void**)&p_tt,   g_tt);
    cudaGetSymbolAddress((void**)&p_qkvg, g_qkvg);
    cudaGetSymbolAddress((void**)&p_obuf, g_obuf);
    cudaGetSymbolAddress((void**)&p_bm,   g_bm);
    cudaGetSymbolAddress((void**)&p_r1,   g_r1);
    cudaGetSymbolAddress((void**)&p_r2,   g_r2);
    cudaGetSymbolAddress((void**)&p_Wada, g_Wada);
    cudaGetSymbolAddress((void**)&p_Wsig, g_Wsig);
    cudaGetSymbolAddress((void**)&p_bsig, g_bsig);
    cudaGetSymbolAddress((void**)&p_Wqkvg,g_Wqkvg);
    cudaGetSymbolAddress((void**)&p_bqkv, g_bqkv);
    cudaGetSymbolAddress((void**)&p_W12,  g_W12);
    float* p_y2; cudaGetSymbolAddress((void**)&p_y2, g_y2);

    const int PACK_TOTAL = 64*1536 + 64*768 + 768 + 3*128*512 + 3*512 + 3*128*512;
    pack_kernel<<<(PACK_TOTAL + 255)/256, 256>>>(
        attn_s_gamma, attn_gate_w, attn_skip_w,
        trans_s_gamma, trans_gate_w, trans_skip_w,
        attn_ws_out, attn_bs_out, trans_ws_out, trans_bs_out,
        attn_wq, attn_bq, attn_wk, attn_wv, attn_wgate,
        trans_w1, trans_w2);

    lnc_kernel<<<Tv, 64>>>(c);
    tgemm_kernel<<<dim3(1536/128, Tv/128), 256>>>(p_lnc, 64, p_Wada, 1536, p_Yada, nullptr, 0);
    tgemm_kernel<<<dim3(768/128,  Tv/128), 256>>>(c,     64, p_Wsig, 768,  p_Ysig, p_bsig, 1);

    const int ATTN_SMEM = (32*128 + 128*KVS + 4*HSTRIDE + 96) * 4;
    cudaFuncSetAttribute(attn_kernel, cudaFuncAttributeMaxDynamicSharedMemorySize, ATTN_SMEM);

    for (int i = 0; i < 3; ++i) {
        const float* a_in = (i == 0) ? q : (const float*)out;
        adaln_kernel<<<Tv, 128>>>(a_in, i);
        tgemm_kernel<<<dim3(4, Tv/128), 256>>>(p_ah, 128, p_Wqkvg + (size_t)i*128*512, 512,
                                               p_qkvg, p_bqkv + i*512, 0);
        tgemm_kernel<<<dim3(4, Tv/128), 256>>>(p_tt, 128, p_W12 + (size_t)i*128*512, 512,
                                               p_y2, nullptr, 0);
        attn_kernel<<<dim3(32, Bv), 256, ATTN_SMEM>>>(p, attn_lnz_g + i*16,
                                                      attn_lnz_b + i*16, attn_wb + i*64);
        bm_kernel<<<(Tv*256)/256, 256>>>();
        tgemm_kernel<<<dim3(1, Tv/128), 256>>>(p_obuf, 128, attn_wo + (size_t)i*128*128, 128,
                                               p_r1, nullptr, 0);
        tgemm_kernel<<<dim3(1, Tv/128), 256>>>(p_bm, 256, trans_wout + (size_t)i*256*128, 128,
                                               p_r2, nullptr, 0);
        final_kernel<<<Tv, 128>>>(out, i);
    }
}